// round 1
// baseline (speedup 1.0000x reference)
#include <cuda_runtime.h>
#include <math.h>

// Problem dims
#define BATCH 2048
#define TLEN  80
#define EDIM  100
#define UNITS 512
#define KTOT  612     // 512 (W_hh) + 100 (W_xh)
#define KPAD  624     // padded to multiple of BK

// GEMM tiling
#define BM 128
#define BN 64
#define BK 16

// Static device scratch (no allocations allowed)
__device__ float g_H[2][BATCH * UNITS];     // ping-pong hidden state
__device__ float g_W[KPAD * UNITS];         // stacked [W_hh ; W_xh ; 0-pad]

// ---- packed f32x2 helpers (sm_100+) ----
#define FMA2(c, a, b) \
    asm("fma.rn.f32x2 %0, %1, %2, %0;" : "+l"(c) : "l"(a), "l"(b))
#define PACK2(d, s) \
    asm("mov.b64 %0, {%1, %1};" : "=l"(d) : "f"(s))
#define UNPACK2(lo, hi, v) \
    asm("mov.b64 {%0, %1}, %2;" : "=f"(lo), "=f"(hi) : "l"(v))

// Build stacked weight matrix: rows [0,512) = W_hh, [512,612) = W_xh, rest 0.
__global__ void build_w_kernel(const float* __restrict__ Whh,
                               const float* __restrict__ Wxh) {
    int i = blockIdx.x * blockDim.x + threadIdx.x;
    if (i >= KPAD * UNITS) return;
    int k = i / UNITS;
    int n = i - k * UNITS;
    float v = 0.0f;
    if (k < 512)      v = Whh[k * UNITS + n];
    else if (k < 612) v = Wxh[(k - 512) * UNITS + n];
    g_W[i] = v;
}

// h0 = 0
__global__ void init_h_kernel() {
    int i = blockIdx.x * blockDim.x + threadIdx.x;
    if (i < BATCH * UNITS) g_H[0][i] = 0.0f;
}

// One recurrence step:
//   H_next = tanh( [H | emb[inputs[:,t]]] @ g_W + b_h )
// Tiled fp32x2 GEMM. Grid: (UNITS/BN, BATCH/BM) = (8, 16), 256 threads.
__global__ __launch_bounds__(256)
void rnn_step_kernel(const int*   __restrict__ inputs,
                     const float* __restrict__ emb,
                     const float* __restrict__ bh,
                     int t) {
    const float* __restrict__ Hsrc = g_H[t & 1];
    float*       __restrict__ Hdst = g_H[(t + 1) & 1];

    __shared__ __align__(16) float As[BK][BM + 4];  // +4 pad: stride 132 floats (16B-aligned)
    __shared__ __align__(16) float Bs[BK][BN];
    __shared__ int idxs[BM];

    const int tid  = threadIdx.x;
    const int row0 = blockIdx.y * BM;
    const int col0 = blockIdx.x * BN;

    if (tid < BM) idxs[tid] = inputs[(row0 + tid) * TLEN + t];
    __syncthreads();

    unsigned long long acc[4][4];
#pragma unroll
    for (int i = 0; i < 4; i++)
#pragma unroll
        for (int j = 0; j < 4; j++) acc[i][j] = 0ULL;

    const int tx = tid & 15;       // n-direction
    const int ty = tid >> 4;       // m-direction
    const int m0 = ty * 8;
    const int n0 = tx * 4;

    for (int k0 = 0; k0 < KPAD; k0 += BK) {
        // ---- load A tile (128 x 16): H columns or embedding gather ----
        {
            const int kk  = tid & 15;
            const int mb  = tid >> 4;
            const int col = k0 + kk;
#pragma unroll
            for (int p = 0; p < 8; p++) {
                int m = mb + p * 16;
                float v = 0.0f;
                if (col < 512) {
                    v = Hsrc[(row0 + m) * UNITS + col];
                } else if (col < 612) {
                    v = emb[idxs[m] * EDIM + (col - 512)];
                }
                As[kk][m] = v;
            }
        }
        // ---- load B tile (16 x 64), coalesced ----
        {
            const int n  = tid & 63;
            const int kb = tid >> 6;
#pragma unroll
            for (int p = 0; p < 4; p++) {
                int kk = kb + p * 4;
                Bs[kk][n] = g_W[(k0 + kk) * UNITS + col0 + n];
            }
        }
        __syncthreads();

#pragma unroll
        for (int kk = 0; kk < BK; kk++) {
            // a: 8 consecutive m values -> 4 m-pairs (packed f32x2 directly from SMEM)
            const unsigned long long* ap =
                reinterpret_cast<const unsigned long long*>(&As[kk][m0]);
            unsigned long long a0 = ap[0], a1 = ap[1], a2 = ap[2], a3 = ap[3];
            // b: 4 n values, broadcast-packed
            float4 bv = *reinterpret_cast<const float4*>(&Bs[kk][n0]);
            unsigned long long b0, b1, b2, b3;
            PACK2(b0, bv.x); PACK2(b1, bv.y); PACK2(b2, bv.z); PACK2(b3, bv.w);

            FMA2(acc[0][0], a0, b0); FMA2(acc[0][1], a0, b1);
            FMA2(acc[0][2], a0, b2); FMA2(acc[0][3], a0, b3);
            FMA2(acc[1][0], a1, b0); FMA2(acc[1][1], a1, b1);
            FMA2(acc[1][2], a1, b2); FMA2(acc[1][3], a1, b3);
            FMA2(acc[2][0], a2, b0); FMA2(acc[2][1], a2, b1);
            FMA2(acc[2][2], a2, b2); FMA2(acc[2][3], a2, b3);
            FMA2(acc[3][0], a3, b0); FMA2(acc[3][1], a3, b1);
            FMA2(acc[3][2], a3, b2); FMA2(acc[3][3], a3, b3);
        }
        __syncthreads();
    }

    // ---- epilogue: + b_h, tanh, store ----
    float bhv[4];
#pragma unroll
    for (int j = 0; j < 4; j++) bhv[j] = bh[col0 + n0 + j];

#pragma unroll
    for (int i = 0; i < 4; i++) {
        float lo[4], hi[4];
#pragma unroll
        for (int j = 0; j < 4; j++) UNPACK2(lo[j], hi[j], acc[i][j]);
        int r = row0 + m0 + 2 * i;
        float4 o0, o1;
        o0.x = tanhf(lo[0] + bhv[0]); o0.y = tanhf(lo[1] + bhv[1]);
        o0.z = tanhf(lo[2] + bhv[2]); o0.w = tanhf(lo[3] + bhv[3]);
        o1.x = tanhf(hi[0] + bhv[0]); o1.y = tanhf(hi[1] + bhv[1]);
        o1.z = tanhf(hi[2] + bhv[2]); o1.w = tanhf(hi[3] + bhv[3]);
        *reinterpret_cast<float4*>(&Hdst[r * UNITS + col0 + n0])       = o0;
        *reinterpret_cast<float4*>(&Hdst[(r + 1) * UNITS + col0 + n0]) = o1;
    }
}

// out = sigmoid(h_last @ W_out + b_out); h_last lives in g_H[0] (80 is even).
__global__ __launch_bounds__(256)
void final_logits_kernel(const float* __restrict__ Wout,
                         const float* __restrict__ bout,
                         float* __restrict__ out) {
    const float* __restrict__ h = g_H[0];
    int warp = threadIdx.x >> 5;
    int lane = threadIdx.x & 31;
    int row  = blockIdx.x * 8 + warp;
    if (row >= BATCH) return;
    float s = 0.0f;
#pragma unroll
    for (int j = 0; j < UNITS / 32; j++) {
        int k = lane + j * 32;
        s += h[row * UNITS + k] * Wout[k];
    }
#pragma unroll
    for (int o = 16; o; o >>= 1) s += __shfl_xor_sync(0xffffffff, s, o);
    if (lane == 0) out[row] = 1.0f / (1.0f + expf(-(s + bout[0])));
}

extern "C" void kernel_launch(void* const* d_in, const int* in_sizes, int n_in,
                              void* d_out, int out_size) {
    const int*   inputs = (const int*)  d_in[0];
    const float* emb    = (const float*)d_in[1];
    const float* Wxh    = (const float*)d_in[2];
    const float* Whh    = (const float*)d_in[3];
    const float* bh     = (const float*)d_in[4];
    const float* Wout   = (const float*)d_in[5];
    const float* bout   = (const float*)d_in[6];
    float* out = (float*)d_out;

    build_w_kernel<<<(KPAD * UNITS + 255) / 256, 256>>>(Whh, Wxh);
    init_h_kernel<<<(BATCH * UNITS + 255) / 256, 256>>>();

    dim3 grid(UNITS / BN, BATCH / BM);  // (8, 16)
    for (int t = 0; t < TLEN; t++) {
        rnn_step_kernel<<<grid, 256>>>(inputs, emb, bh, t);
    }

    final_logits_kernel<<<BATCH / 8, 256>>>(Wout, bout, out);
}

// round 3
// speedup vs baseline: 5.4696x; 5.4696x over previous
#include <cuda_runtime.h>
#include <cuda_bf16.h>
#include <cstdint>
#include <math.h>

// ---------------- problem dims ----------------
#define BATCH 2048
#define TLEN  80
#define EDIM  100
#define UNITS 512
#define DPAD  128              // embedding K padded 100 -> 128
#define KTOT  (UNITS + DPAD)   // 640
#define KC    64               // K chunk (64 bf16 = 128 B row)
#define NCHUNK (KTOT / KC)     // 10
#define BM    128
#define BN    64

// ---------------- static device scratch ----------------
__device__ __nv_bfloat16 g_Hhi[2][BATCH * UNITS];
__device__ __nv_bfloat16 g_Hlo[2][BATCH * UNITS];
__device__ __nv_bfloat16 g_Xhi[(size_t)TLEN * BATCH * DPAD];
__device__ __nv_bfloat16 g_Xlo[(size_t)TLEN * BATCH * DPAD];
__device__ __nv_bfloat16 g_Wbhi[UNITS * KTOT];   // B-operand layout: [n][k]
__device__ __nv_bfloat16 g_Wblo[UNITS * KTOT];

// ---------------- PTX helpers (arch-agnostic: sm_80-class) ----------------
__device__ __forceinline__ uint32_t smem_to_u32(const void* p) {
    uint32_t a;
    asm("{ .reg .u64 t; cvta.to.shared.u64 t, %1; cvt.u32.u64 %0, t; }" : "=r"(a) : "l"(p));
    return a;
}
#define CP16(dst, src) \
    asm volatile("cp.async.cg.shared.global [%0], [%1], 16;" :: "r"(dst), "l"(src))
#define CP_COMMIT() asm volatile("cp.async.commit_group;" ::: "memory")
#define CP_WAIT(n)  asm volatile("cp.async.wait_group %0;" :: "n"(n) : "memory")

#define LDSM_X4(r0, r1, r2, r3, addr) \
    asm volatile("ldmatrix.sync.aligned.m8n8.x4.shared.b16 {%0,%1,%2,%3}, [%4];" \
                 : "=r"(r0), "=r"(r1), "=r"(r2), "=r"(r3) : "r"(addr))

#define MMA16816(d, a0, a1, a2, a3, b0, b1) \
    asm volatile("mma.sync.aligned.m16n8k16.row.col.f32.bf16.bf16.f32 " \
                 "{%0,%1,%2,%3}, {%4,%5,%6,%7}, {%8,%9}, {%0,%1,%2,%3};" \
                 : "+f"((d)[0]), "+f"((d)[1]), "+f"((d)[2]), "+f"((d)[3]) \
                 : "r"(a0), "r"(a1), "r"(a2), "r"(a3), "r"(b0), "r"(b1))

#define SWZ(bo) ((bo) ^ (((bo) >> 3) & 0x70))

// ---------------- dynamic SMEM layout ----------------
// A tiles: buf x plane x 16KB ; B tiles: buf x plane x 8KB
#define A_OFF(buf, plane) (((buf) * 2 + (plane)) * 16384)
#define B_OFF(buf, plane) (65536 + ((buf) * 2 + (plane)) * 8192)
#define SMEM_TOTAL (65536 + 4 * 8192)   // 98304 B

// ---------------- prep kernels ----------------
__global__ void prep_x_kernel(const int* __restrict__ inputs,
                              const float* __restrict__ emb) {
    size_t i = (size_t)blockIdx.x * blockDim.x + threadIdx.x;
    if (i >= (size_t)TLEN * BATCH * DPAD) return;
    int d = (int)(i & (DPAD - 1));
    size_t bt = i >> 7;                 // t*BATCH + b
    int b = (int)(bt & (BATCH - 1));
    int t = (int)(bt >> 11);            // BATCH = 2048 = 2^11
    float x = 0.0f;
    if (d < EDIM) {
        int idx = inputs[(size_t)b * TLEN + t];
        x = emb[(size_t)idx * EDIM + d];
    }
    __nv_bfloat16 hi = __float2bfloat16(x);
    __nv_bfloat16 lo = __float2bfloat16(x - __bfloat162float(hi));
    g_Xhi[i] = hi;
    g_Xlo[i] = lo;
}

__global__ void build_w_kernel(const float* __restrict__ Whh,
                               const float* __restrict__ Wxh) {
    int i = blockIdx.x * blockDim.x + threadIdx.x;
    if (i >= UNITS * KTOT) return;
    int n = i / KTOT;
    int k = i - n * KTOT;
    float v = 0.0f;
    if (k < UNITS)             v = Whh[(size_t)k * UNITS + n];
    else if (k < UNITS + EDIM) v = Wxh[(size_t)(k - UNITS) * UNITS + n];
    __nv_bfloat16 hi = __float2bfloat16(v);
    __nv_bfloat16 lo = __float2bfloat16(v - __bfloat162float(hi));
    g_Wbhi[i] = hi;
    g_Wblo[i] = lo;
}

__global__ void init_h_kernel() {
    int i = blockIdx.x * blockDim.x + threadIdx.x;
    if (i >= BATCH * UNITS) return;
    g_Hhi[0][i] = __float2bfloat16(0.0f);
    g_Hlo[0][i] = __float2bfloat16(0.0f);
}

// ---------------- recurrence step (mma.sync bf16 hi/lo split) ----------------
// H_next = tanh( [H | X_t] @ Wstack + b_h )
__global__ __launch_bounds__(256, 1)
void rnn_step_mma(const float* __restrict__ bh, int t) {
    extern __shared__ char smem[];
    const uint32_t su = smem_to_u32(smem);
    const int tid  = threadIdx.x;
    const int wid  = tid >> 5;
    const int lane = tid & 31;

    const int row0 = blockIdx.y * BM;
    const int col0 = blockIdx.x * BN;
    const __nv_bfloat16* __restrict__ Hh = g_Hhi[t & 1];
    const __nv_bfloat16* __restrict__ Hl = g_Hlo[t & 1];
    const __nv_bfloat16* __restrict__ Xh = g_Xhi + (size_t)t * BATCH * DPAD;
    const __nv_bfloat16* __restrict__ Xl = g_Xlo + (size_t)t * BATCH * DPAD;

    // ---- async chunk loader ----
    auto load_chunk = [&](int c, int buf) {
        const int k0 = c * KC;
        const __nv_bfloat16 *sh, *sl;
        int stride;
        if (k0 < UNITS) {
            sh = Hh + (size_t)row0 * UNITS + k0;
            sl = Hl + (size_t)row0 * UNITS + k0;
            stride = UNITS;
        } else {
            sh = Xh + (size_t)row0 * DPAD + (k0 - UNITS);
            sl = Xl + (size_t)row0 * DPAD + (k0 - UNITS);
            stride = DPAD;
        }
#pragma unroll
        for (int i = 0; i < 4; i++) {                 // A: 1024 16B units
            int u = tid + i * 256;
            int r = u >> 3, s = u & 7;
            uint32_t so = SWZ((uint32_t)(r * 128 + s * 16));
            CP16(su + A_OFF(buf, 0) + so, (const char*)(sh + (size_t)r * stride) + s * 16);
            CP16(su + A_OFF(buf, 1) + so, (const char*)(sl + (size_t)r * stride) + s * 16);
        }
        const __nv_bfloat16* wh = g_Wbhi + (size_t)col0 * KTOT + k0;
        const __nv_bfloat16* wl = g_Wblo + (size_t)col0 * KTOT + k0;
#pragma unroll
        for (int i = 0; i < 2; i++) {                 // B: 512 16B units
            int u = tid + i * 256;
            int r = u >> 3, s = u & 7;
            uint32_t so = SWZ((uint32_t)(r * 128 + s * 16));
            CP16(su + B_OFF(buf, 0) + so, (const char*)(wh + (size_t)r * KTOT) + s * 16);
            CP16(su + B_OFF(buf, 1) + so, (const char*)(wl + (size_t)r * KTOT) + s * 16);
        }
        CP_COMMIT();
    };

    // warp tiling: 4 warps in M x 2 in N; warp tile 32(M) x 32(N)
    const int m_base = (wid & 3) * 32;
    const int n_base = (wid >> 2) * 32;

    // ldmatrix base byte offsets (per lane, within a plane)
    // A frag (m16 tile mt): row = m_base + mt*16 + (lane&15), k-half = lane>>4
    const int a_row  = (lane & 15);
    const int a_kh   = (lane >> 4) * 16;              // bytes
    // B frag pair (np covers two n8 tiles): row = n_base + np*16 + ((lane>>4)<<3) + (lane&7)
    const int b_row  = ((lane >> 4) << 3) + (lane & 7);
    const int b_kh   = ((lane >> 3) & 1) * 16;        // bytes

    float acc[2][4][4];
#pragma unroll
    for (int i = 0; i < 2; i++)
#pragma unroll
        for (int j = 0; j < 4; j++)
#pragma unroll
            for (int q = 0; q < 4; q++) acc[i][j][q] = 0.0f;

    load_chunk(0, 0);

    for (int c = 0; c < NCHUNK; c++) {
        const int buf = c & 1;
        if (c + 1 < NCHUNK) {
            load_chunk(c + 1, (c + 1) & 1);
            CP_WAIT(1);
        } else {
            CP_WAIT(0);
        }
        __syncthreads();

        const uint32_t ah = su + A_OFF(buf, 0);
        const uint32_t al = su + A_OFF(buf, 1);
        const uint32_t bhp = su + B_OFF(buf, 0);
        const uint32_t blp = su + B_OFF(buf, 1);

#pragma unroll
        for (int ks = 0; ks < 4; ks++) {
            const int kb = ks * 32;                   // byte offset of k0 within row

            uint32_t Ah[2][4], Al[2][4];
#pragma unroll
            for (int mt = 0; mt < 2; mt++) {
                uint32_t bo = SWZ((uint32_t)((m_base + mt * 16 + a_row) * 128 + kb + a_kh));
                LDSM_X4(Ah[mt][0], Ah[mt][1], Ah[mt][2], Ah[mt][3], ah + bo);
                LDSM_X4(Al[mt][0], Al[mt][1], Al[mt][2], Al[mt][3], al + bo);
            }
            uint32_t Bh[4][2], Bl[4][2];
#pragma unroll
            for (int np = 0; np < 2; np++) {
                uint32_t bo = SWZ((uint32_t)((n_base + np * 16 + b_row) * 128 + kb + b_kh));
                LDSM_X4(Bh[np * 2][0], Bh[np * 2][1], Bh[np * 2 + 1][0], Bh[np * 2 + 1][1], bhp + bo);
                LDSM_X4(Bl[np * 2][0], Bl[np * 2][1], Bl[np * 2 + 1][0], Bl[np * 2 + 1][1], blp + bo);
            }
#pragma unroll
            for (int mt = 0; mt < 2; mt++) {
#pragma unroll
                for (int nt = 0; nt < 4; nt++) {
                    MMA16816(acc[mt][nt], Ah[mt][0], Ah[mt][1], Ah[mt][2], Ah[mt][3],
                             Bh[nt][0], Bh[nt][1]);
                    MMA16816(acc[mt][nt], Ah[mt][0], Ah[mt][1], Ah[mt][2], Ah[mt][3],
                             Bl[nt][0], Bl[nt][1]);
                    MMA16816(acc[mt][nt], Al[mt][0], Al[mt][1], Al[mt][2], Al[mt][3],
                             Bh[nt][0], Bh[nt][1]);
                }
            }
        }
        __syncthreads();
    }

    // ---- epilogue: + b_h, tanh, hi/lo split, store ----
    __nv_bfloat16* __restrict__ dhP = g_Hhi[(t + 1) & 1];
    __nv_bfloat16* __restrict__ dlP = g_Hlo[(t + 1) & 1];
    const int g   = lane >> 2;
    const int tig = lane & 3;
#pragma unroll
    for (int mt = 0; mt < 2; mt++) {
#pragma unroll
        for (int nt = 0; nt < 4; nt++) {
            const int col = col0 + n_base + nt * 8 + tig * 2;
            const float b0 = __ldg(bh + col);
            const float b1 = __ldg(bh + col + 1);
#pragma unroll
            for (int half = 0; half < 2; half++) {
                const int row = row0 + m_base + mt * 16 + g + half * 8;
                float v0 = tanhf(acc[mt][nt][half * 2 + 0] + b0);
                float v1 = tanhf(acc[mt][nt][half * 2 + 1] + b1);
                __nv_bfloat16 h0 = __float2bfloat16(v0);
                __nv_bfloat16 h1 = __float2bfloat16(v1);
                __nv_bfloat16 l0 = __float2bfloat16(v0 - __bfloat162float(h0));
                __nv_bfloat16 l1 = __float2bfloat16(v1 - __bfloat162float(h1));
                __nv_bfloat162 hp; hp.x = h0; hp.y = h1;
                __nv_bfloat162 lp; lp.x = l0; lp.y = l1;
                *reinterpret_cast<__nv_bfloat162*>(dhP + (size_t)row * UNITS + col) = hp;
                *reinterpret_cast<__nv_bfloat162*>(dlP + (size_t)row * UNITS + col) = lp;
            }
        }
    }
}

// ---------------- final logits ----------------
__global__ __launch_bounds__(256)
void final_logits_kernel(const float* __restrict__ Wout,
                         const float* __restrict__ bout,
                         float* __restrict__ out) {
    const __nv_bfloat16* __restrict__ hh = g_Hhi[0];  // TLEN=80 even -> plane 0
    const __nv_bfloat16* __restrict__ hl = g_Hlo[0];
    int warp = threadIdx.x >> 5;
    int lane = threadIdx.x & 31;
    int row = blockIdx.x * 8 + warp;
    if (row >= BATCH) return;
    float s = 0.0f;
#pragma unroll
    for (int j = 0; j < UNITS / 32; j++) {
        int k = lane + j * 32;
        float h = __bfloat162float(hh[(size_t)row * UNITS + k]) +
                  __bfloat162float(hl[(size_t)row * UNITS + k]);
        s += h * Wout[k];
    }
#pragma unroll
    for (int o = 16; o; o >>= 1) s += __shfl_xor_sync(0xffffffff, s, o);
    if (lane == 0) out[row] = 1.0f / (1.0f + expf(-(s + bout[0])));
}

// ---------------- launch ----------------
extern "C" void kernel_launch(void* const* d_in, const int* in_sizes, int n_in,
                              void* d_out, int out_size) {
    const int*   inputs = (const int*)  d_in[0];
    const float* emb    = (const float*)d_in[1];
    const float* Wxh    = (const float*)d_in[2];
    const float* Whh    = (const float*)d_in[3];
    const float* bh     = (const float*)d_in[4];
    const float* Wout   = (const float*)d_in[5];
    const float* bout   = (const float*)d_in[6];
    float* out = (float*)d_out;

    cudaFuncSetAttribute(rnn_step_mma,
                         cudaFuncAttributeMaxDynamicSharedMemorySize, SMEM_TOTAL);

    {
        size_t n = (size_t)TLEN * BATCH * DPAD;
        prep_x_kernel<<<(unsigned)((n + 255) / 256), 256>>>(inputs, emb);
    }
    build_w_kernel<<<(UNITS * KTOT + 255) / 256, 256>>>(Whh, Wxh);
    init_h_kernel<<<(BATCH * UNITS + 255) / 256, 256>>>();

    dim3 grid(UNITS / BN, BATCH / BM);   // (8, 16) = 128 CTAs
    for (int t = 0; t < TLEN; t++) {
        rnn_step_mma<<<grid, 256, SMEM_TOTAL>>>(bh, t);
    }

    final_logits_kernel<<<BATCH / 8, 256>>>(Wout, bout, out);
}